// round 2
// baseline (speedup 1.0000x reference)
#include <cuda_runtime.h>
#include <math.h>

#define NSd   12
#define NCd   4
#define Td    32
#define NZd   512          // T * 16
#define NEQ   384          // NS * T
#define NIN   128          // T * NC
#define DAMPv 1e-4f
#define LS    17           // padded row stride (bank-conflict-free)

struct Smem {
    float M[192];           // [A|B] row-major, 12x16
    float MtM[256];         // M^T M
    float x0[12];
    float z[NZd];
    float Qd[NZd];
    float cd[NZd];
    float g[NZd];           // gradient -> y -> dz (in place)
    float lamE[NEQ];
    float lamU[NIN];
    float lamL[NIN];
    float lo[NIN];
    float up[NIN];
    float Yv[NEQ];
    float P[16 * LS];       // staging for current diagonal block
    float Linv[Td * 16 * LS]; // L^{-1} per block (lower, upper zeroed)
    float W[Td * 12 * LS];  // W_t = -rho*M*Linv_{t-1}^T
};

__global__ __launch_bounds__(32, 1)
void mpc_kernel(const float* __restrict__ x0g, const float* __restrict__ Qg,
                const float* __restrict__ cg,  const float* __restrict__ Ag,
                const float* __restrict__ Bg,  const float* __restrict__ log_,
                const float* __restrict__ upg, float* __restrict__ out, int NB)
{
    extern __shared__ float smraw[];
    Smem* S = reinterpret_cast<Smem*>(smraw);
    const int b    = blockIdx.x;
    const int lane = threadIdx.x;

    // ---------------- load inputs ----------------
    for (int i = lane; i < NZd; i += 32) {
        S->z[i]  = 0.f;
        S->Qd[i] = Qg[b * NZd + i];
        S->cd[i] = cg[b * NZd + i];
    }
    for (int i = lane; i < NEQ; i += 32) S->lamE[i] = 0.f;
    for (int i = lane; i < NIN; i += 32) {
        S->lamU[i] = 0.f; S->lamL[i] = 0.f;
        S->lo[i] = log_[b * NIN + i];
        S->up[i] = upg[b * NIN + i];
    }
    for (int i = lane; i < 192; i += 32) {
        int r = i / 16, cc = i % 16;
        S->M[i] = (cc < 12) ? Ag[r * 12 + cc] : Bg[r * 4 + (cc - 12)];
    }
    if (lane < 12) S->x0[lane] = x0g[b * 12 + lane];
    __syncwarp();

    // ---------------- MtM ----------------
    for (int i = lane; i < 256; i += 32) {
        int ii = i >> 4, jj = i & 15;
        float a = 0.f;
        #pragma unroll
        for (int k = 0; k < 12; ++k) a += S->M[k * 16 + ii] * S->M[k * 16 + jj];
        S->MtM[i] = a;
    }

    // ---------------- initial rollout x_t = A^t x0 ----------------
    if (lane < 12) S->z[lane] = S->x0[lane];
    for (int t = 0; t < Td - 1; ++t) {
        __syncwarp();
        if (lane < 12) {
            float acc = 0.f;
            #pragma unroll
            for (int j = 0; j < 12; ++j) acc += S->M[lane * 16 + j] * S->z[t * 16 + j];
            S->z[(t + 1) * 16 + lane] = acc;
        }
    }
    __syncwarp();

    float rho = 1.f;
    for (int al = 0; al < 3; ++al) {
        for (int nt = 0; nt < 3; ++nt) {
            // ---- Yv = rho*r + lamE ----
            for (int idx = lane; idx < NEQ; idx += 32) {
                int t = idx / 12, i = idx % 12;
                float r;
                if (t == 0) r = S->z[i] - S->x0[i];
                else {
                    float acc = S->z[t * 16 + i];
                    const float* zp = &S->z[(t - 1) * 16];
                    const float* Mr = &S->M[i * 16];
                    #pragma unroll
                    for (int k = 0; k < 16; ++k) acc -= Mr[k] * zp[k];
                    r = acc;
                }
                S->Yv[idx] = rho * r + S->lamE[idx];
            }
            __syncwarp();
            // ---- gradient ----
            for (int idx = lane; idx < NZd; idx += 32) {
                int t = idx >> 4, i = idx & 15;
                float gv = S->Qd[idx] * S->z[idx] + S->cd[idx];
                if (i < 12) gv += S->Yv[t * 12 + i];
                if (t < Td - 1) {
                    const float* Yn = &S->Yv[(t + 1) * 12];
                    float acc = 0.f;
                    #pragma unroll
                    for (int k = 0; k < 12; ++k) acc += S->M[k * 16 + i] * Yn[k];
                    gv -= acc;
                }
                if (i >= 12) {
                    int u = t * 4 + (i - 12);
                    float uv = S->z[idx];
                    float su = fmaxf(rho * (uv - S->up[u]) + S->lamU[u], 0.f);
                    float sl = fmaxf(rho * (S->lo[u] - uv) + S->lamL[u], 0.f);
                    gv += su - sl;
                }
                S->g[idx] = gv;
            }
            __syncwarp();

            // ---- factorization over t (warp-synchronous, no bar.sync) ----
            for (int t = 0; t < Td; ++t) {
                if (t > 0) {
                    // W_t = -rho * M * Linv_{t-1}^T  (parallel matmul)
                    const float* Lp = &S->Linv[(t - 1) * 16 * LS];
                    float* Wt = &S->W[t * 12 * LS];
                    for (int idx = lane; idx < 192; idx += 32) {
                        int i = idx >> 4, j = idx & 15;
                        float acc = 0.f;
                        #pragma unroll
                        for (int k = 0; k < 16; ++k) acc += S->M[i * 16 + k] * Lp[j * LS + k];
                        Wt[i * LS + j] = -rho * acc;
                    }
                    __syncwarp();
                }
                // build P_t = D_t - W_t W_t^T (lower triangle)
                {
                    const float* Wt = &S->W[t * 12 * LS];
                    for (int idx = lane; idx < 256; idx += 32) {
                        int i = idx >> 4, j = idx & 15;
                        if (j > i) continue;
                        float v = (t < Td - 1) ? rho * S->MtM[i * 16 + j] : 0.f;
                        if (i == j) {
                            v += S->Qd[t * 16 + i] + DAMPv;
                            if (i < 12) v += rho;
                            else {
                                int u = t * 4 + (i - 12);
                                float uv = S->z[t * 16 + i];
                                if (rho * (uv - S->up[u]) + S->lamU[u] > 0.f) v += rho;
                                if (rho * (S->lo[u] - uv) + S->lamL[u] > 0.f) v += rho;
                            }
                        }
                        if (t > 0 && i < 12 && j < 12) {
                            float a = 0.f;
                            #pragma unroll
                            for (int k = 0; k < 16; ++k) a += Wt[i * LS + k] * Wt[j * LS + k];
                            v -= a;
                        }
                        S->P[i * LS + j] = v;
                    }
                }
                __syncwarp();
                // fused Cholesky + Linv (lanes 0-15, register rows + shuffles)
                if (lane < 16) {
                    float r[16], v[16];
                    #pragma unroll
                    for (int j = 0; j < 16; ++j) {
                        r[j] = S->P[lane * LS + j];          // valid for j<=lane
                        v[j] = (j == lane) ? 1.f : 0.f;
                    }
                    #pragma unroll
                    for (int k = 0; k < 16; ++k) {
                        float dk  = __shfl_sync(0xffffu, r[k], k);
                        float inv = 1.0f / sqrtf(dk);
                        if (lane > k) r[k] *= inv;           // true L[lane][k]
                        if (lane == k) {
                            #pragma unroll
                            for (int j = 0; j <= k; ++j) v[j] *= inv;
                        }
                        // Cholesky trailing update
                        #pragma unroll
                        for (int j = k + 1; j < 16; ++j) {
                            float ljk = __shfl_sync(0xffffu, r[k], j);
                            if (lane >= j) r[j] -= r[k] * ljk;
                        }
                        // Linv accumulation (eliminate below row k)
                        #pragma unroll
                        for (int j = 0; j <= k; ++j) {
                            float vkj = __shfl_sync(0xffffu, v[j], k);
                            if (lane > k) v[j] -= r[k] * vkj;
                        }
                    }
                    float* Li = &S->Linv[t * 16 * LS + lane * LS];
                    #pragma unroll
                    for (int j = 0; j < 16; ++j) Li[j] = (j <= lane) ? v[j] : 0.f;
                }
                __syncwarp();
            }

            // ---- substitution: matvecs with Linv (lanes 0-15) ----
            if (lane < 16) {
                // forward: y_t = Linv_t (g_t - W_t y_{t-1})
                for (int t = 0; t < Td; ++t) {
                    float d = S->g[t * 16 + lane];
                    if (t > 0 && lane < 12) {
                        const float* Wt = &S->W[t * 12 * LS + lane * LS];
                        const float* yp = &S->g[(t - 1) * 16];
                        #pragma unroll
                        for (int k = 0; k < 16; ++k) d -= Wt[k] * yp[k];
                    }
                    const float* Li = &S->Linv[t * 16 * LS + lane * LS];
                    float y = 0.f;
                    #pragma unroll
                    for (int k = 0; k < 16; ++k) {
                        float dk = __shfl_sync(0xffffu, d, k);
                        y += Li[k] * dk;                     // Li[k]=0 for k>lane
                    }
                    S->g[t * 16 + lane] = y;
                    __syncwarp(0xffffu);
                }
                // backward: dz_t = Linv_t^T (y_t - W_{t+1}^T dz_{t+1})
                for (int t = Td - 1; t >= 0; --t) {
                    float vv = S->g[t * 16 + lane];
                    if (t < Td - 1) {
                        const float* Wn  = &S->W[(t + 1) * 12 * LS];
                        const float* dzn = &S->g[(t + 1) * 16];
                        #pragma unroll
                        for (int k = 0; k < 12; ++k) vv -= Wn[k * LS + lane] * dzn[k];
                    }
                    const float* Lc = &S->Linv[t * 16 * LS];
                    float dz = 0.f;
                    #pragma unroll
                    for (int k = 0; k < 16; ++k) {
                        float vk = __shfl_sync(0xffffu, vv, k);
                        dz += Lc[k * LS + lane] * vk;        // zero for k<lane
                    }
                    S->g[t * 16 + lane] = dz;
                    __syncwarp(0xffffu);
                }
            }
            __syncwarp();
            // ---- z -= dz ----
            for (int idx = lane; idx < NZd; idx += 32) S->z[idx] -= S->g[idx];
            __syncwarp();
        } // newton

        // ---- multiplier updates ----
        for (int idx = lane; idx < NEQ; idx += 32) {
            int t = idx / 12, i = idx % 12;
            float r;
            if (t == 0) r = S->z[i] - S->x0[i];
            else {
                float acc = S->z[t * 16 + i];
                const float* zp = &S->z[(t - 1) * 16];
                const float* Mr = &S->M[i * 16];
                #pragma unroll
                for (int k = 0; k < 16; ++k) acc -= Mr[k] * zp[k];
                r = acc;
            }
            S->lamE[idx] += rho * r;
        }
        for (int idx = lane; idx < NIN; idx += 32) {
            int t = idx >> 2, j = idx & 3;
            float uv = S->z[t * 16 + 12 + j];
            S->lamU[idx] = fmaxf(S->lamU[idx] + rho * (uv - S->up[idx]), 0.f);
            S->lamL[idx] = fmaxf(S->lamL[idx] + rho * (S->lo[idx] - uv), 0.f);
        }
        __syncwarp();
        rho = fminf(rho * 10.f, 100.f);
    } // al

    // ---------------- outputs: x [NB,T,NS] then u [NB,T,NC] ----------------
    for (int idx = lane; idx < NEQ; idx += 32) {
        int t = idx / 12, i = idx % 12;
        out[b * (Td * NSd) + idx] = S->z[t * 16 + i];
    }
    for (int idx = lane; idx < NIN; idx += 32) {
        int t = idx >> 2, j = idx & 3;
        out[NB * (Td * NSd) + b * (Td * NCd) + idx] = S->z[t * 16 + 12 + j];
    }
}

extern "C" void kernel_launch(void* const* d_in, const int* in_sizes, int n_in,
                              void* d_out, int out_size)
{
    const float* x0 = (const float*)d_in[0];
    const float* Q  = (const float*)d_in[1];
    const float* c  = (const float*)d_in[2];
    const float* A  = (const float*)d_in[3];
    const float* B  = (const float*)d_in[4];
    const float* lo = (const float*)d_in[5];
    const float* up = (const float*)d_in[6];
    float* out = (float*)d_out;

    int NB = in_sizes[0] / NSd;   // 64
    size_t smem = sizeof(Smem);
    cudaFuncSetAttribute(mpc_kernel, cudaFuncAttributeMaxDynamicSharedMemorySize, (int)smem);
    mpc_kernel<<<NB, 32, smem>>>(x0, Q, c, A, B, lo, up, out, NB);
}

// round 3
// speedup vs baseline: 1.4875x; 1.4875x over previous
#include <cuda_runtime.h>
#include <math.h>

#define NSd   12
#define NCd   4
#define Td    32
#define NZd   512          // T * 16
#define NEQ   384          // NS * T
#define NIN   128          // T * NC
#define DAMPv 1e-4f
#define LS    17           // padded row stride (bank-conflict-free)

struct Smem {
    float M[192];             // [A|B] row-major, 12x16
    float MtM[256];           // M^T M
    float x0[12];
    float z[NZd];
    float Qd[NZd];
    float cd[NZd];
    float g[NZd];             // gradient -> y -> dz (in place)
    float lamE[NEQ];
    float lamU[NIN];
    float lamL[NIN];
    float lo[NIN];
    float up[NIN];
    float Yv[NEQ];
    float P[16 * LS];         // staging for current diagonal block
    float Linv[Td * 16 * LS]; // L^{-1} per block (lower; upper zeroed)
    float W[Td * 12 * LS];    // W_t = -rho * M * Linv_{t-1}^T
};

__global__ __launch_bounds__(256, 1)
void mpc_kernel(const float* __restrict__ x0g, const float* __restrict__ Qg,
                const float* __restrict__ cg,  const float* __restrict__ Ag,
                const float* __restrict__ Bg,  const float* __restrict__ log_,
                const float* __restrict__ upg, float* __restrict__ out, int NB)
{
    extern __shared__ float smraw[];
    Smem* S = reinterpret_cast<Smem*>(smraw);
    const int b   = blockIdx.x;
    const int tid = threadIdx.x;

    // ---------------- load inputs ----------------
    for (int i = tid; i < NZd; i += 256) {
        S->z[i]  = 0.f;
        S->Qd[i] = Qg[b * NZd + i];
        S->cd[i] = cg[b * NZd + i];
    }
    for (int i = tid; i < NEQ; i += 256) S->lamE[i] = 0.f;
    for (int i = tid; i < NIN; i += 256) {
        S->lamU[i] = 0.f; S->lamL[i] = 0.f;
        S->lo[i] = log_[b * NIN + i];
        S->up[i] = upg[b * NIN + i];
    }
    if (tid < 192) {
        int r = tid / 16, cc = tid % 16;
        S->M[tid] = (cc < 12) ? Ag[r * 12 + cc] : Bg[r * 4 + (cc - 12)];
    }
    if (tid < 12) S->x0[tid] = x0g[b * 12 + tid];
    __syncthreads();

    // ---------------- MtM (1 elem/thread) ----------------
    {
        int ii = tid >> 4, jj = tid & 15;
        float a = 0.f;
        #pragma unroll
        for (int k = 0; k < 12; ++k) a += S->M[k * 16 + ii] * S->M[k * 16 + jj];
        S->MtM[tid] = a;
    }

    // ---------------- initial rollout x_t = A^t x0 (warp 0) ----------------
    if (tid < 32) {
        if (tid < 12) S->z[tid] = S->x0[tid];
        for (int t = 0; t < Td - 1; ++t) {
            __syncwarp();
            if (tid < 12) {
                float acc = 0.f;
                #pragma unroll
                for (int j = 0; j < 12; ++j) acc += S->M[tid * 16 + j] * S->z[t * 16 + j];
                S->z[(t + 1) * 16 + tid] = acc;
            }
        }
    }
    __syncthreads();

    float rho = 1.f;
    for (int al = 0; al < 3; ++al) {
        for (int nt = 0; nt < 3; ++nt) {
            // ---- Yv = rho*r + lamE ----
            for (int idx = tid; idx < NEQ; idx += 256) {
                int t = idx / 12, i = idx % 12;
                float r;
                if (t == 0) r = S->z[i] - S->x0[i];
                else {
                    float acc = S->z[t * 16 + i];
                    const float* zp = &S->z[(t - 1) * 16];
                    const float* Mr = &S->M[i * 16];
                    #pragma unroll
                    for (int k = 0; k < 16; ++k) acc -= Mr[k] * zp[k];
                    r = acc;
                }
                S->Yv[idx] = rho * r + S->lamE[idx];
            }
            __syncthreads();
            // ---- gradient ----
            for (int idx = tid; idx < NZd; idx += 256) {
                int t = idx >> 4, i = idx & 15;
                float gv = S->Qd[idx] * S->z[idx] + S->cd[idx];
                if (i < 12) gv += S->Yv[t * 12 + i];
                if (t < Td - 1) {
                    const float* Yn = &S->Yv[(t + 1) * 12];
                    float acc = 0.f;
                    #pragma unroll
                    for (int k = 0; k < 12; ++k) acc += S->M[k * 16 + i] * Yn[k];
                    gv -= acc;
                }
                if (i >= 12) {
                    int u = t * 4 + (i - 12);
                    float uv = S->z[idx];
                    float su = fmaxf(rho * (uv - S->up[u]) + S->lamU[u], 0.f);
                    float sl = fmaxf(rho * (S->lo[u] - uv) + S->lamL[u], 0.f);
                    gv += su - sl;
                }
                S->g[idx] = gv;
            }
            __syncthreads();

            // ---- block factorization: 3 barriers per t ----
            for (int t = 0; t < Td; ++t) {
                // phase 1: W_t = -rho * M * Linv_{t-1}^T (parallel matmul, 192 threads)
                if (t > 0 && tid < 192) {
                    int i = tid >> 4, j = tid & 15;
                    const float* Lp = &S->Linv[(t - 1) * 16 * LS];
                    float acc = 0.f;
                    #pragma unroll
                    for (int k = 0; k < 16; ++k) acc += S->M[i * 16 + k] * Lp[j * LS + k];
                    S->W[t * 12 * LS + i * LS + j] = -rho * acc;
                }
                __syncthreads();
                // phase 2: P_t = D_t - W_t W_t^T (lower triangle, 1 elem/thread)
                {
                    int i = tid >> 4, j = tid & 15;
                    if (j <= i) {
                        float v = (t < Td - 1) ? rho * S->MtM[i * 16 + j] : 0.f;
                        if (i == j) {
                            v += S->Qd[t * 16 + i] + DAMPv;
                            if (i < 12) v += rho;
                            else {
                                int u = t * 4 + (i - 12);
                                float uv = S->z[t * 16 + i];
                                if (rho * (uv - S->up[u]) + S->lamU[u] > 0.f) v += rho;
                                if (rho * (S->lo[u] - uv) + S->lamL[u] > 0.f) v += rho;
                            }
                        }
                        if (t > 0 && i < 12 && j < 12) {
                            const float* Wt = &S->W[t * 12 * LS];
                            float a = 0.f;
                            #pragma unroll
                            for (int k = 0; k < 16; ++k) a += Wt[i * LS + k] * Wt[j * LS + k];
                            v -= a;
                        }
                        S->P[i * LS + j] = v;
                    }
                }
                __syncthreads();
                // phase 3: fused Cholesky + Linv (warp 0, lanes 0-15; no barriers)
                if (tid < 16) {
                    float r[16], v[16];
                    #pragma unroll
                    for (int j = 0; j < 16; ++j) {
                        r[j] = S->P[tid * LS + j];       // valid for j<=tid
                        v[j] = (j == tid) ? 1.f : 0.f;
                    }
                    #pragma unroll
                    for (int k = 0; k < 16; ++k) {
                        float dk  = __shfl_sync(0xffffu, r[k], k);
                        float inv = rsqrtf(dk);
                        if (tid > k) r[k] *= inv;        // true L[tid][k]
                        if (tid == k) {
                            #pragma unroll
                            for (int j = 0; j <= k; ++j) v[j] *= inv;
                        }
                        #pragma unroll
                        for (int j = k + 1; j < 16; ++j) {
                            float ljk = __shfl_sync(0xffffu, r[k], j);
                            if (tid >= j) r[j] -= r[k] * ljk;
                        }
                        #pragma unroll
                        for (int j = 0; j <= k; ++j) {
                            float vkj = __shfl_sync(0xffffu, v[j], k);
                            if (tid > k) v[j] -= r[k] * vkj;
                        }
                    }
                    float* Li = &S->Linv[t * 16 * LS + tid * LS];
                    #pragma unroll
                    for (int j = 0; j < 16; ++j) Li[j] = (j <= tid) ? v[j] : 0.f;
                }
                __syncthreads();
            }

            // ---- substitution: warp 0 lanes 0-15, Linv matvecs ----
            if (tid < 16) {
                const int lane = tid;
                // forward: y_t = Linv_t (g_t - W_t y_{t-1})
                for (int t = 0; t < Td; ++t) {
                    float d = S->g[t * 16 + lane];
                    if (t > 0 && lane < 12) {
                        const float* Wt = &S->W[t * 12 * LS + lane * LS];
                        const float* yp = &S->g[(t - 1) * 16];
                        #pragma unroll
                        for (int k = 0; k < 16; ++k) d -= Wt[k] * yp[k];
                    }
                    const float* Li = &S->Linv[t * 16 * LS + lane * LS];
                    float y = 0.f;
                    #pragma unroll
                    for (int k = 0; k < 16; ++k) {
                        float dk = __shfl_sync(0xffffu, d, k);
                        y += Li[k] * dk;                 // Li[k]=0 for k>lane
                    }
                    S->g[t * 16 + lane] = y;
                    __syncwarp(0xffffu);
                }
                // backward: dz_t = Linv_t^T (y_t - W_{t+1}^T dz_{t+1})
                for (int t = Td - 1; t >= 0; --t) {
                    float vv = S->g[t * 16 + lane];
                    if (t < Td - 1) {
                        const float* Wn  = &S->W[(t + 1) * 12 * LS];
                        const float* dzn = &S->g[(t + 1) * 16];
                        #pragma unroll
                        for (int k = 0; k < 12; ++k) vv -= Wn[k * LS + lane] * dzn[k];
                    }
                    const float* Lc = &S->Linv[t * 16 * LS];
                    float dz = 0.f;
                    #pragma unroll
                    for (int k = 0; k < 16; ++k) {
                        float vk = __shfl_sync(0xffffu, vv, k);
                        dz += Lc[k * LS + lane] * vk;    // zero for k<lane
                    }
                    S->g[t * 16 + lane] = dz;
                    __syncwarp(0xffffu);
                }
            }
            __syncthreads();
            // ---- z -= dz ----
            for (int idx = tid; idx < NZd; idx += 256) S->z[idx] -= S->g[idx];
            __syncthreads();
        } // newton

        // ---- multiplier updates ----
        for (int idx = tid; idx < NEQ; idx += 256) {
            int t = idx / 12, i = idx % 12;
            float r;
            if (t == 0) r = S->z[i] - S->x0[i];
            else {
                float acc = S->z[t * 16 + i];
                const float* zp = &S->z[(t - 1) * 16];
                const float* Mr = &S->M[i * 16];
                #pragma unroll
                for (int k = 0; k < 16; ++k) acc -= Mr[k] * zp[k];
                r = acc;
            }
            S->lamE[idx] += rho * r;
        }
        for (int idx = tid; idx < NIN; idx += 256) {
            int t = idx >> 2, j = idx & 3;
            float uv = S->z[t * 16 + 12 + j];
            S->lamU[idx] = fmaxf(S->lamU[idx] + rho * (uv - S->up[idx]), 0.f);
            S->lamL[idx] = fmaxf(S->lamL[idx] + rho * (S->lo[idx] - uv), 0.f);
        }
        __syncthreads();
        rho = fminf(rho * 10.f, 100.f);
    } // al

    // ---------------- outputs: x [NB,T,NS] then u [NB,T,NC] ----------------
    for (int idx = tid; idx < NEQ; idx += 256) {
        int t = idx / 12, i = idx % 12;
        out[b * (Td * NSd) + idx] = S->z[t * 16 + i];
    }
    for (int idx = tid; idx < NIN; idx += 256) {
        int t = idx >> 2, j = idx & 3;
        out[NB * (Td * NSd) + b * (Td * NCd) + idx] = S->z[t * 16 + 12 + j];
    }
}

extern "C" void kernel_launch(void* const* d_in, const int* in_sizes, int n_in,
                              void* d_out, int out_size)
{
    const float* x0 = (const float*)d_in[0];
    const float* Q  = (const float*)d_in[1];
    const float* c  = (const float*)d_in[2];
    const float* A  = (const float*)d_in[3];
    const float* B  = (const float*)d_in[4];
    const float* lo = (const float*)d_in[5];
    const float* up = (const float*)d_in[6];
    float* out = (float*)d_out;

    int NB = in_sizes[0] / NSd;   // 64
    size_t smem = sizeof(Smem);
    cudaFuncSetAttribute(mpc_kernel, cudaFuncAttributeMaxDynamicSharedMemorySize, (int)smem);
    mpc_kernel<<<NB, 256, smem>>>(x0, Q, c, A, B, lo, up, out, NB);
}

// round 4
// speedup vs baseline: 4.2669x; 2.8685x over previous
#include <cuda_runtime.h>
#include <math.h>

#define NSd   12
#define NCd   4
#define Td    32
#define NZd   512          // T * 16
#define NEQ   384          // NS * T
#define NIN   128          // T * NC
#define DAMPv 1e-4f
#define LS    17           // padded row stride

struct Smem {
    float M[192];             // [A|B] row-major, 12x16
    float MtM[256];           // M^T M
    float x0[12];
    float z[NZd];
    float Qd[NZd];
    float cd[NZd];
    float g[NZd];             // gradient -> w -> dz (in place)
    float Pw[NZd];            // Pinv_t * w_t (parallel pass)
    float lamE[NEQ];
    float lamU[NIN];
    float lamL[NIN];
    float lo[NIN];
    float up[NIN];
    float Yv[NEQ];
    float P[16 * LS];         // staging for current diagonal block (full 16x16)
    float Pinv[Td * 16 * LS]; // P_t^{-1} per block
    float U[Td * 16 * LS];    // U_t = rho * M * Pinv_{t-1}, rows 12-15 zeroed
    int   act[NIN];           // active-set signature used in last factorization
};

__global__ __launch_bounds__(256, 1)
void mpc_kernel(const float* __restrict__ x0g, const float* __restrict__ Qg,
                const float* __restrict__ cg,  const float* __restrict__ Ag,
                const float* __restrict__ Bg,  const float* __restrict__ log_,
                const float* __restrict__ upg, float* __restrict__ out, int NB)
{
    extern __shared__ float smraw[];
    Smem* S = reinterpret_cast<Smem*>(smraw);
    const int b    = blockIdx.x;
    const int tid  = threadIdx.x;
    const int lane = tid & 31;

    // ---------------- load inputs ----------------
    for (int i = tid; i < NZd; i += 256) {
        S->z[i]  = 0.f;
        S->Qd[i] = Qg[b * NZd + i];
        S->cd[i] = cg[b * NZd + i];
    }
    for (int i = tid; i < NEQ; i += 256) S->lamE[i] = 0.f;
    for (int i = tid; i < NIN; i += 256) {
        S->lamU[i] = 0.f; S->lamL[i] = 0.f;
        S->lo[i]  = log_[b * NIN + i];
        S->up[i]  = upg[b * NIN + i];
        S->act[i] = -1;
    }
    if (tid < 192) {
        int r = tid / 16, cc = tid % 16;
        S->M[tid] = (cc < 12) ? Ag[r * 12 + cc] : Bg[r * 4 + (cc - 12)];
    }
    if (tid < 12) S->x0[tid] = x0g[b * 12 + tid];
    __syncthreads();

    // ---------------- MtM ----------------
    {
        int ii = tid >> 4, jj = tid & 15;
        float a = 0.f;
        #pragma unroll
        for (int k = 0; k < 12; ++k) a += S->M[k * 16 + ii] * S->M[k * 16 + jj];
        S->MtM[tid] = a;
    }

    // ---------------- initial rollout x_t = A^t x0 (warp 0) ----------------
    if (tid < 32) {
        if (tid < 12) S->z[tid] = S->x0[tid];
        for (int t = 0; t < Td - 1; ++t) {
            __syncwarp();
            if (tid < 12) {
                float acc = 0.f;
                #pragma unroll
                for (int j = 0; j < 12; ++j) acc += S->M[tid * 16 + j] * S->z[t * 16 + j];
                S->z[(t + 1) * 16 + tid] = acc;
            }
        }
    }
    __syncthreads();

    float rho = 1.f;
    for (int al = 0; al < 3; ++al) {
        for (int nt = 0; nt < 3; ++nt) {
            // ---- Yv = rho*r + lamE ----
            for (int idx = tid; idx < NEQ; idx += 256) {
                int t = idx / 12, i = idx % 12;
                float r;
                if (t == 0) r = S->z[i] - S->x0[i];
                else {
                    float acc = S->z[t * 16 + i];
                    const float* zp = &S->z[(t - 1) * 16];
                    const float* Mr = &S->M[i * 16];
                    #pragma unroll
                    for (int k = 0; k < 16; ++k) acc -= Mr[k] * zp[k];
                    r = acc;
                }
                S->Yv[idx] = rho * r + S->lamE[idx];
            }
            __syncthreads();
            // ---- gradient + active-set change detection ----
            int myChanged = 0;
            for (int idx = tid; idx < NZd; idx += 256) {
                int t = idx >> 4, i = idx & 15;
                float gv = S->Qd[idx] * S->z[idx] + S->cd[idx];
                if (i < 12) gv += S->Yv[t * 12 + i];
                if (t < Td - 1) {
                    const float* Yn = &S->Yv[(t + 1) * 12];
                    float acc = 0.f;
                    #pragma unroll
                    for (int k = 0; k < 12; ++k) acc += S->M[k * 16 + i] * Yn[k];
                    gv -= acc;
                }
                if (i >= 12) {
                    int u = t * 4 + (i - 12);
                    float su = fmaxf(rho * (S->z[idx] - S->up[u]) + S->lamU[u], 0.f);
                    float sl = fmaxf(rho * (S->lo[u] - S->z[idx]) + S->lamL[u], 0.f);
                    gv += su - sl;
                    int a = (su > 0.f ? 1 : 0) | (sl > 0.f ? 2 : 0);
                    if (a != S->act[u]) { myChanged = 1; S->act[u] = a; }
                }
                S->g[idx] = gv;
            }
            int anyChanged = __syncthreads_or(myChanged);   // also a barrier
            bool needFactor = (nt == 0) || anyChanged;

            if (needFactor) {
                for (int t = 0; t < Td; ++t) {
                    // phase 1: U_t = rho * M * Pinv_{t-1} (rows>=12 zero)
                    if (t > 0) {
                        int i = tid >> 4, j = tid & 15;
                        float v = 0.f;
                        if (i < 12) {
                            const float* Pp = &S->Pinv[(t - 1) * 16 * LS];
                            const float* Mr = &S->M[i * 16];
                            float acc = 0.f;
                            #pragma unroll
                            for (int m = 0; m < 16; ++m) acc += Mr[m] * Pp[j * LS + m]; // Pinv sym
                            v = rho * acc;
                        }
                        S->U[t * 16 * LS + i * LS + j] = v;
                        __syncthreads();
                    }
                    // phase 2: P_t = D_t - rho * U_t M^T (full 16x16)
                    {
                        int i = tid >> 4, j = tid & 15;
                        float v = (t < Td - 1) ? rho * S->MtM[i * 16 + j] : 0.f;
                        if (i == j) {
                            v += S->Qd[t * 16 + i] + DAMPv;
                            if (i < 12) v += rho;
                            else {
                                int a = S->act[t * 4 + (i - 12)];
                                if (a & 1) v += rho;
                                if (a & 2) v += rho;
                            }
                        }
                        if (t > 0 && i < 12 && j < 12) {
                            const float* Ur = &S->U[t * 16 * LS + i * LS];
                            const float* Mr = &S->M[j * 16];
                            float acc = 0.f;
                            #pragma unroll
                            for (int k = 0; k < 16; ++k) acc += Ur[k] * Mr[k];
                            v -= rho * acc;
                        }
                        S->P[i * LS + j] = v;
                    }
                    __syncthreads();
                    // phase 3: warp 0 Gauss-Jordan inversion (branch-free)
                    if (tid < 32) {
                        float a[16];
                        #pragma unroll
                        for (int j = 0; j < 16; ++j)
                            a[j] = S->P[(lane & 15) * LS + j];
                        #pragma unroll
                        for (int k = 0; k < 16; ++k) {
                            float p   = __shfl_sync(0xffffffffu, a[k], k);
                            float inv = __fdividef(1.0f, p);
                            float f   = a[k];
                            float fi  = f * inv;
                            bool  isk = ((lane & 15) == k);
                            #pragma unroll
                            for (int j = 0; j < 16; ++j) {
                                float rkj = __shfl_sync(0xffffffffu, a[j], k);
                                float rs  = rkj * inv;         // new row-k entry
                                float upd = a[j] - fi * rkj;   // trailing update
                                a[j] = isk ? rs : upd;
                            }
                            a[k] = isk ? inv : -fi;
                        }
                        if (lane < 16) {
                            float* Pi = &S->Pinv[t * 16 * LS + lane * LS];
                            #pragma unroll
                            for (int j = 0; j < 16; ++j) Pi[j] = a[j];
                        }
                    }
                    __syncthreads();
                }
            }

            // ---- forward: w_t = g_t + U_t w_{t-1} (warp 0) ----
            if (tid < 32) {
                float w = (lane < 16) ? S->g[lane] : 0.f;   // t = 0
                for (int t = 1; t < Td; ++t) {
                    __syncwarp();
                    float gv = (lane < 16) ? S->g[t * 16 + lane] : 0.f;
                    const float* Ur = &S->U[t * 16 * LS + (lane & 15) * LS];
                    float acc = 0.f;
                    #pragma unroll
                    for (int k = 0; k < 16; ++k) {
                        float wk = __shfl_sync(0xffffffffu, w, k);
                        acc += Ur[k] * wk;                   // rows >=12 are zero
                    }
                    w = gv + acc;
                    if (lane < 16) S->g[t * 16 + lane] = w;
                }
            }
            __syncthreads();
            // ---- parallel pass: Pw_t = Pinv_t w_t ----
            for (int idx = tid; idx < NZd; idx += 256) {
                int t = idx >> 4, i = idx & 15;
                const float* Pi = &S->Pinv[t * 16 * LS + i * LS];
                const float* wv = &S->g[t * 16];
                float acc = 0.f;
                #pragma unroll
                for (int k = 0; k < 16; ++k) acc += Pi[k] * wv[k];
                S->Pw[idx] = acc;
            }
            __syncthreads();
            // ---- backward: dz_t = Pw_t + U_{t+1}^T dz_{t+1} (warp 0) ----
            if (tid < 32) {
                float dz = (lane < 16) ? S->Pw[(Td - 1) * 16 + lane] : 0.f;
                if (lane < 16) S->g[(Td - 1) * 16 + lane] = dz;
                for (int t = Td - 2; t >= 0; --t) {
                    __syncwarp();
                    const float* Uc = &S->U[(t + 1) * 16 * LS];
                    float acc = (lane < 16) ? S->Pw[t * 16 + lane] : 0.f;
                    #pragma unroll
                    for (int k = 0; k < 12; ++k) {
                        float dk = __shfl_sync(0xffffffffu, dz, k);
                        acc += Uc[k * LS + (lane & 15)] * dk;
                    }
                    dz = acc;
                    if (lane < 16) S->g[t * 16 + lane] = dz;
                }
            }
            __syncthreads();
            // ---- z -= dz ----
            for (int idx = tid; idx < NZd; idx += 256) S->z[idx] -= S->g[idx];
            __syncthreads();
        } // newton

        // ---- multiplier updates ----
        for (int idx = tid; idx < NEQ; idx += 256) {
            int t = idx / 12, i = idx % 12;
            float r;
            if (t == 0) r = S->z[i] - S->x0[i];
            else {
                float acc = S->z[t * 16 + i];
                const float* zp = &S->z[(t - 1) * 16];
                const float* Mr = &S->M[i * 16];
                #pragma unroll
                for (int k = 0; k < 16; ++k) acc -= Mr[k] * zp[k];
                r = acc;
            }
            S->lamE[idx] += rho * r;
        }
        for (int idx = tid; idx < NIN; idx += 256) {
            int t = idx >> 2, j = idx & 3;
            float uv = S->z[t * 16 + 12 + j];
            S->lamU[idx] = fmaxf(S->lamU[idx] + rho * (uv - S->up[idx]), 0.f);
            S->lamL[idx] = fmaxf(S->lamL[idx] + rho * (S->lo[idx] - uv), 0.f);
        }
        __syncthreads();
        rho = fminf(rho * 10.f, 100.f);
    } // al

    // ---------------- outputs: x [NB,T,NS] then u [NB,T,NC] ----------------
    for (int idx = tid; idx < NEQ; idx += 256) {
        int t = idx / 12, i = idx % 12;
        out[b * (Td * NSd) + idx] = S->z[t * 16 + i];
    }
    for (int idx = tid; idx < NIN; idx += 256) {
        int t = idx >> 2, j = idx & 3;
        out[NB * (Td * NSd) + b * (Td * NCd) + idx] = S->z[t * 16 + 12 + j];
    }
}

extern "C" void kernel_launch(void* const* d_in, const int* in_sizes, int n_in,
                              void* d_out, int out_size)
{
    const float* x0 = (const float*)d_in[0];
    const float* Q  = (const float*)d_in[1];
    const float* c  = (const float*)d_in[2];
    const float* A  = (const float*)d_in[3];
    const float* B  = (const float*)d_in[4];
    const float* lo = (const float*)d_in[5];
    const float* up = (const float*)d_in[6];
    float* out = (float*)d_out;

    int NB = in_sizes[0] / NSd;   // 64
    size_t smem = sizeof(Smem);
    cudaFuncSetAttribute(mpc_kernel, cudaFuncAttributeMaxDynamicSharedMemorySize, (int)smem);
    mpc_kernel<<<NB, 256, smem>>>(x0, Q, c, A, B, lo, up, out, NB);
}

// round 5
// speedup vs baseline: 6.7579x; 1.5838x over previous
#include <cuda_runtime.h>
#include <math.h>

#define NSd   12
#define NCd   4
#define Td    32
#define NZd   512          // T * 16
#define NEQ   384
#define NIN   128
#define DAMPv 1e-4f
#define LS    17           // padded row stride

struct Smem {
    float M[192];             // [A|B] row-major, 12x16
    float MtM[256];
    float x0[12];
    float z[NZd], Qd[NZd], cd[NZd], g[NZd], Pw[NZd];
    float lamE[NEQ], lamU[NIN], lamL[NIN], lo[NIN], up[NIN];
    float Yv[NEQ];
    float Pa[16 * LS], Pb[16 * LS];
    float inv[32 * 16 * LS];  // t<=16: Pinv (fwd);  t>=17: Qbinv (bwd)
    float Uf[17 * 16 * LS];   // Uf[t] = rho*M*Pinv_{t-1}, rows>=12 zero, t=1..16
    float Ub[31 * 16 * LS];   // Ub[t] = rho*M^T*S*Qbinv_{t+1}, full 16x16, t=16..30
    int   act[NIN];
};

__device__ __forceinline__ float buildD(const Smem* S, int t, int i, int j, float rho) {
    float v = (t < Td - 1) ? rho * S->MtM[i * 16 + j] : 0.f;
    if (i == j) {
        v += S->Qd[t * 16 + i] + DAMPv;
        if (i < 12) v += rho;
        else {
            int a = S->act[t * 4 + (i - 12)];
            if (a & 1) v += rho;
            if (a & 2) v += rho;
        }
    }
    return v;
}

// branch-free Gauss-Jordan 16x16 inversion on one warp (lanes mirror via &15)
__device__ __forceinline__ void gj16(const float* Psrc, float* dst, int lane) {
    const int l = lane & 15;
    float a[16];
    #pragma unroll
    for (int j = 0; j < 16; ++j) a[j] = Psrc[l * LS + j];
    #pragma unroll
    for (int k = 0; k < 16; ++k) {
        float p   = __shfl_sync(0xffffffffu, a[k], k);
        float inv = __fdividef(1.0f, p);
        float fi  = a[k] * inv;
        bool  isk = (l == k);
        #pragma unroll
        for (int j = 0; j < 16; ++j) {
            float rkj = __shfl_sync(0xffffffffu, a[j], k);
            float rs  = rkj * inv;
            float upd = a[j] - fi * rkj;
            a[j] = isk ? rs : upd;
        }
        a[k] = isk ? inv : -fi;
    }
    if (lane < 16) {
        #pragma unroll
        for (int j = 0; j < 16; ++j) dst[l * LS + j] = a[j];
    }
}

__global__ __launch_bounds__(256, 1)
void mpc_kernel(const float* __restrict__ x0g, const float* __restrict__ Qg,
                const float* __restrict__ cg,  const float* __restrict__ Ag,
                const float* __restrict__ Bg,  const float* __restrict__ log_,
                const float* __restrict__ upg, float* __restrict__ out, int NB)
{
    extern __shared__ float smraw[];
    Smem* S = reinterpret_cast<Smem*>(smraw);
    const int b    = blockIdx.x;
    const int tid  = threadIdx.x;
    const int wid  = tid >> 5;
    const int lane = tid & 31;
    const int ri   = tid >> 4;    // 16x16 element row
    const int rj   = tid & 15;    // 16x16 element col

    // ---------------- load inputs ----------------
    for (int i = tid; i < NZd; i += 256) {
        S->z[i]  = 0.f;
        S->Qd[i] = Qg[b * NZd + i];
        S->cd[i] = cg[b * NZd + i];
    }
    for (int i = tid; i < NEQ; i += 256) S->lamE[i] = 0.f;
    for (int i = tid; i < NIN; i += 256) {
        S->lamU[i] = 0.f; S->lamL[i] = 0.f;
        S->lo[i]  = log_[b * NIN + i];
        S->up[i]  = upg[b * NIN + i];
        S->act[i] = -1;
    }
    if (tid < 192) {
        int r = tid / 16, cc = tid % 16;
        S->M[tid] = (cc < 12) ? Ag[r * 12 + cc] : Bg[r * 4 + (cc - 12)];
    }
    if (tid < 12) S->x0[tid] = x0g[b * 12 + tid];
    __syncthreads();

    // ---------------- MtM ----------------
    {
        float a = 0.f;
        #pragma unroll
        for (int k = 0; k < 12; ++k) a += S->M[k * 16 + ri] * S->M[k * 16 + rj];
        S->MtM[tid] = a;
    }

    // ---------------- initial rollout (warp 0) ----------------
    if (tid < 32) {
        if (tid < 12) S->z[tid] = S->x0[tid];
        for (int t = 0; t < Td - 1; ++t) {
            __syncwarp();
            if (tid < 12) {
                float acc = 0.f;
                #pragma unroll
                for (int j = 0; j < 12; ++j) acc += S->M[tid * 16 + j] * S->z[t * 16 + j];
                S->z[(t + 1) * 16 + tid] = acc;
            }
        }
    }
    __syncthreads();

    float rho = 1.f;
    for (int al = 0; al < 3; ++al) {
        for (int nt = 0; nt < 3; ++nt) {
            // ---- Yv = rho*r + lamE ----
            for (int idx = tid; idx < NEQ; idx += 256) {
                int t = idx / 12, i = idx % 12;
                float r;
                if (t == 0) r = S->z[i] - S->x0[i];
                else {
                    float acc = S->z[t * 16 + i];
                    const float* zp = &S->z[(t - 1) * 16];
                    const float* Mr = &S->M[i * 16];
                    #pragma unroll
                    for (int k = 0; k < 16; ++k) acc -= Mr[k] * zp[k];
                    r = acc;
                }
                S->Yv[idx] = rho * r + S->lamE[idx];
            }
            __syncthreads();
            // ---- gradient + active-set change detection ----
            int myChanged = 0;
            for (int idx = tid; idx < NZd; idx += 256) {
                int t = idx >> 4, i = idx & 15;
                float gv = S->Qd[idx] * S->z[idx] + S->cd[idx];
                if (i < 12) gv += S->Yv[t * 12 + i];
                if (t < Td - 1) {
                    const float* Yn = &S->Yv[(t + 1) * 12];
                    float acc = 0.f;
                    #pragma unroll
                    for (int k = 0; k < 12; ++k) acc += S->M[k * 16 + i] * Yn[k];
                    gv -= acc;
                }
                if (i >= 12) {
                    int u = t * 4 + (i - 12);
                    float su = fmaxf(rho * (S->z[idx] - S->up[u]) + S->lamU[u], 0.f);
                    float sl = fmaxf(rho * (S->lo[u] - S->z[idx]) + S->lamL[u], 0.f);
                    gv += su - sl;
                    int a = (su > 0.f ? 1 : 0) | (sl > 0.f ? 2 : 0);
                    if (a != S->act[u]) { myChanged = 1; S->act[u] = a; }
                }
                S->g[idx] = gv;
            }
            int anyChanged = __syncthreads_or(myChanged);
            bool needFactor = (nt == 0) || anyChanged;

            if (needFactor) {
                // ---- twisted factorization: fwd t=0..15 & bwd t=31..17 concurrently ----
                for (int s = 0; s < 16; ++s) {
                    int tf = s, tb = 31 - s;
                    bool doB = (s < 15);
                    if (s > 0) {
                        // Uf[tf][ri][rj] = rho * sum_m M[ri][m] * Pinv_{tf-1}[m][rj]
                        float v = 0.f;
                        if (ri < 12) {
                            const float* Pp = &S->inv[(tf - 1) * 16 * LS];
                            const float* Mr = &S->M[ri * 16];
                            float a0 = 0.f, a1 = 0.f;
                            #pragma unroll
                            for (int m = 0; m < 16; m += 2) {
                                a0 += Mr[m]     * Pp[m * LS + rj];
                                a1 += Mr[m + 1] * Pp[(m + 1) * LS + rj];
                            }
                            v = rho * (a0 + a1);
                        }
                        S->Uf[tf * 16 * LS + ri * LS + rj] = v;
                        if (doB) {
                            // Ub[tb][ri][rj] = rho * sum_{m<12} M[m][ri] * Qbinv_{tb+1}[m][rj]
                            const float* Qp = &S->inv[(tb + 1) * 16 * LS];
                            float a0 = 0.f, a1 = 0.f;
                            #pragma unroll
                            for (int m = 0; m < 12; m += 2) {
                                a0 += S->M[m * 16 + ri]       * Qp[m * LS + rj];
                                a1 += S->M[(m + 1) * 16 + ri] * Qp[(m + 1) * LS + rj];
                            }
                            S->Ub[tb * 16 * LS + ri * LS + rj] = rho * (a0 + a1);
                        }
                        __syncwarp();
                    }
                    // Pa = D_tf - rho * Uf M^T  (i<12,j<12 block)
                    {
                        float v = buildD(S, tf, ri, rj, rho);
                        if (s > 0 && ri < 12 && rj < 12) {
                            const float* Ur = &S->Uf[tf * 16 * LS + ri * LS];
                            const float* Mr = &S->M[rj * 16];
                            float a0 = 0.f, a1 = 0.f;
                            #pragma unroll
                            for (int k = 0; k < 16; k += 2) { a0 += Ur[k] * Mr[k]; a1 += Ur[k+1] * Mr[k+1]; }
                            v -= rho * (a0 + a1);
                        }
                        S->Pa[ri * LS + rj] = v;
                    }
                    if (doB) {
                        float v = buildD(S, tb, ri, rj, rho);
                        if (s > 0) {
                            const float* Ur = &S->Ub[tb * 16 * LS + ri * LS];
                            float a0 = 0.f, a1 = 0.f;
                            #pragma unroll
                            for (int k = 0; k < 12; k += 2) {
                                a0 += Ur[k]     * S->M[k * 16 + rj];
                                a1 += Ur[k + 1] * S->M[(k + 1) * 16 + rj];
                            }
                            v -= rho * (a0 + a1);
                        }
                        S->Pb[ri * LS + rj] = v;
                    }
                    __syncthreads();
                    if (wid == 0)            gj16(S->Pa, &S->inv[tf * 16 * LS], lane);
                    else if (wid == 1 && doB) gj16(S->Pb, &S->inv[tb * 16 * LS], lane);
                    __syncthreads();
                }
                // ---- middle block m=16 ----
                {
                    float v = 0.f;
                    if (ri < 12) {
                        const float* Pp = &S->inv[15 * 16 * LS];
                        const float* Mr = &S->M[ri * 16];
                        float a0 = 0.f, a1 = 0.f;
                        #pragma unroll
                        for (int m = 0; m < 16; m += 2) {
                            a0 += Mr[m] * Pp[m * LS + rj];
                            a1 += Mr[m + 1] * Pp[(m + 1) * LS + rj];
                        }
                        v = rho * (a0 + a1);
                    }
                    S->Uf[16 * 16 * LS + ri * LS + rj] = v;
                    {
                        const float* Qp = &S->inv[17 * 16 * LS];
                        float a0 = 0.f, a1 = 0.f;
                        #pragma unroll
                        for (int m = 0; m < 12; m += 2) {
                            a0 += S->M[m * 16 + ri] * Qp[m * LS + rj];
                            a1 += S->M[(m + 1) * 16 + ri] * Qp[(m + 1) * LS + rj];
                        }
                        S->Ub[16 * 16 * LS + ri * LS + rj] = rho * (a0 + a1);
                    }
                    __syncwarp();
                    float pv = buildD(S, 16, ri, rj, rho);
                    if (ri < 12 && rj < 12) {
                        const float* Ur = &S->Uf[16 * 16 * LS + ri * LS];
                        const float* Mr = &S->M[rj * 16];
                        float a0 = 0.f;
                        #pragma unroll
                        for (int k = 0; k < 16; ++k) a0 += Ur[k] * Mr[k];
                        pv -= rho * a0;
                    }
                    {
                        const float* Ur = &S->Ub[16 * 16 * LS + ri * LS];
                        float a0 = 0.f;
                        #pragma unroll
                        for (int k = 0; k < 12; ++k) a0 += Ur[k] * S->M[k * 16 + rj];
                        pv -= rho * a0;
                    }
                    S->Pa[ri * LS + rj] = pv;
                    __syncthreads();
                    if (wid == 0) gj16(S->Pa, &S->inv[16 * 16 * LS], lane);
                    __syncthreads();
                }
            }

            // ---- elimination sweeps (warp 0 fwd, warp 1 bwd, concurrent) ----
            if (wid == 0) {
                float w = (lane < 16) ? S->g[lane] : 0.f;           // t=0
                for (int t = 1; t <= 15; ++t) {
                    float gv = (lane < 16) ? S->g[t * 16 + lane] : 0.f;
                    const float* Ur = &S->Uf[t * 16 * LS + (lane & 15) * LS];
                    float a0 = 0.f, a1 = 0.f;
                    #pragma unroll
                    for (int k = 0; k < 16; k += 2) {
                        a0 += Ur[k]     * __shfl_sync(0xffffffffu, w, k);
                        a1 += Ur[k + 1] * __shfl_sync(0xffffffffu, w, k + 1);
                    }
                    w = gv + a0 + a1;                              // rows>=12 of Uf zero
                    if (lane < 16) S->g[t * 16 + lane] = w;
                }
            } else if (wid == 1) {
                float w = (lane < 16) ? S->g[31 * 16 + lane] : 0.f; // t=31
                for (int t = 30; t >= 17; --t) {
                    float gv = (lane < 16) ? S->g[t * 16 + lane] : 0.f;
                    const float* Ur = &S->Ub[t * 16 * LS + (lane & 15) * LS];
                    float a0 = 0.f, a1 = 0.f;
                    #pragma unroll
                    for (int k = 0; k < 16; k += 2) {
                        a0 += Ur[k]     * __shfl_sync(0xffffffffu, w, k);
                        a1 += Ur[k + 1] * __shfl_sync(0xffffffffu, w, k + 1);
                    }
                    w = gv + a0 + a1;
                    if (lane < 16) S->g[t * 16 + lane] = w;
                }
            }
            __syncthreads();
            // ---- middle rhs: w_16 = g_16 + Uf16 w_15 + Ub16 wb_17 (warp 0) ----
            if (wid == 0 && lane < 16) {
                const float* Uf16 = &S->Uf[16 * 16 * LS + lane * LS];
                const float* Ub16 = &S->Ub[16 * 16 * LS + lane * LS];
                const float* w15  = &S->g[15 * 16];
                const float* w17  = &S->g[17 * 16];
                float acc = S->g[16 * 16 + lane];
                #pragma unroll
                for (int k = 0; k < 16; ++k) acc += Uf16[k] * w15[k] + Ub16[k] * w17[k];
                S->g[16 * 16 + lane] = acc;
            }
            __syncthreads();
            // ---- parallel: Pw_t = inv_t * w_t (all 32 t) ----
            for (int idx = tid; idx < NZd; idx += 256) {
                int t = idx >> 4, i = idx & 15;
                const float* Pi = &S->inv[t * 16 * LS + i * LS];
                const float* wv = &S->g[t * 16];
                float a0 = 0.f, a1 = 0.f;
                #pragma unroll
                for (int k = 0; k < 16; k += 2) { a0 += Pi[k] * wv[k]; a1 += Pi[k+1] * wv[k+1]; }
                S->Pw[idx] = a0 + a1;
            }
            __syncthreads();
            // ---- outward passes (warp 0 down, warp 1 up, concurrent) ----
            if (wid == 0) {
                float dz = (lane < 16) ? S->Pw[16 * 16 + lane] : 0.f;
                if (lane < 16) S->g[16 * 16 + lane] = dz;          // final dz_16
                for (int t = 15; t >= 0; --t) {
                    float acc = (lane < 16) ? S->Pw[t * 16 + lane] : 0.f;
                    const float* Uc = &S->Uf[(t + 1) * 16 * LS];
                    #pragma unroll
                    for (int k = 0; k < 12; ++k)
                        acc += Uc[k * LS + (lane & 15)] * __shfl_sync(0xffffffffu, dz, k);
                    dz = acc;
                    if (lane < 16) S->g[t * 16 + lane] = dz;
                }
            } else if (wid == 1) {
                float dz = (lane < 16) ? S->Pw[16 * 16 + lane] : 0.f;
                for (int t = 17; t <= 31; ++t) {
                    float acc = (lane < 16) ? S->Pw[t * 16 + lane] : 0.f;
                    const float* Uc = &S->Ub[(t - 1) * 16 * LS];
                    #pragma unroll
                    for (int k = 0; k < 16; ++k)
                        acc += Uc[k * LS + (lane & 15)] * __shfl_sync(0xffffffffu, dz, k);
                    dz = acc;
                    if (lane < 16) S->g[t * 16 + lane] = dz;
                }
            }
            __syncthreads();
            // ---- z -= dz ----
            for (int idx = tid; idx < NZd; idx += 256) S->z[idx] -= S->g[idx];
            __syncthreads();
        } // newton

        // ---- multiplier updates ----
        for (int idx = tid; idx < NEQ; idx += 256) {
            int t = idx / 12, i = idx % 12;
            float r;
            if (t == 0) r = S->z[i] - S->x0[i];
            else {
                float acc = S->z[t * 16 + i];
                const float* zp = &S->z[(t - 1) * 16];
                const float* Mr = &S->M[i * 16];
                #pragma unroll
                for (int k = 0; k < 16; ++k) acc -= Mr[k] * zp[k];
                r = acc;
            }
            S->lamE[idx] += rho * r;
        }
        for (int idx = tid; idx < NIN; idx += 256) {
            int t = idx >> 2, j = idx & 3;
            float uv = S->z[t * 16 + 12 + j];
            S->lamU[idx] = fmaxf(S->lamU[idx] + rho * (uv - S->up[idx]), 0.f);
            S->lamL[idx] = fmaxf(S->lamL[idx] + rho * (S->lo[idx] - uv), 0.f);
        }
        __syncthreads();
        rho = fminf(rho * 10.f, 100.f);
    } // al

    // ---------------- outputs: x [NB,T,NS] then u [NB,T,NC] ----------------
    for (int idx = tid; idx < NEQ; idx += 256) {
        int t = idx / 12, i = idx % 12;
        out[b * (Td * NSd) + idx] = S->z[t * 16 + i];
    }
    for (int idx = tid; idx < NIN; idx += 256) {
        int t = idx >> 2, j = idx & 3;
        out[NB * (Td * NSd) + b * (Td * NCd) + idx] = S->z[t * 16 + 12 + j];
    }
}

extern "C" void kernel_launch(void* const* d_in, const int* in_sizes, int n_in,
                              void* d_out, int out_size)
{
    const float* x0 = (const float*)d_in[0];
    const float* Q  = (const float*)d_in[1];
    const float* c  = (const float*)d_in[2];
    const float* A  = (const float*)d_in[3];
    const float* B  = (const float*)d_in[4];
    const float* lo = (const float*)d_in[5];
    const float* up = (const float*)d_in[6];
    float* out = (float*)d_out;

    int NB = in_sizes[0] / NSd;   // 64
    size_t smem = sizeof(Smem);
    cudaFuncSetAttribute(mpc_kernel, cudaFuncAttributeMaxDynamicSharedMemorySize, (int)smem);
    mpc_kernel<<<NB, 256, smem>>>(x0, Q, c, A, B, lo, up, out, NB);
}

// round 6
// speedup vs baseline: 8.5009x; 1.2579x over previous
#include <cuda_runtime.h>
#include <math.h>

#define NSd   12
#define NCd   4
#define Td    32
#define NZd   512          // T * 16
#define NEQ   384
#define NIN   128
#define DAMPv 1e-4f
#define LS    17           // padded row stride
#define NTHR  128

struct Smem {
    float M[192];             // [A|B] row-major, 12x16
    float MtM[256];
    float x0[12];
    float z[NZd], Qd[NZd], cd[NZd], g[NZd], Pw[NZd];
    float lamE[NEQ], lamU[NIN], lamL[NIN], lo[NIN], up[NIN];
    float Yv[NEQ];
    float Pa[16 * LS], Pb[16 * LS];
    float inv[32 * 16 * LS];  // t<=16: Pinv (fwd);  t>=17: Qbinv (bwd)
    float Uf[17 * 16 * LS];   // Uf[t] = rho*M*Pinv_{t-1}, rows>=12 zero, t=1..16
    float Ub[31 * 16 * LS];   // Ub[t] = rho*M^T*S*Qbinv_{t+1}, full, t=16..30
    int   act[NIN];
    int   fmin, fmax;         // changed active-set time range this Newton iter
};

__device__ __forceinline__ float buildD(const Smem* S, int t, int i, int j, float rho) {
    float v = (t < Td - 1) ? rho * S->MtM[i * 16 + j] : 0.f;
    if (i == j) {
        v += S->Qd[t * 16 + i] + DAMPv;
        if (i < 12) v += rho;
        else {
            int a = S->act[t * 4 + (i - 12)];
            if (a & 1) v += rho;
            if (a & 2) v += rho;
        }
    }
    return v;
}

// split-lane branch-free Gauss-Jordan: 32 lanes, lane = (row, col-half), 8 cols each
__device__ __forceinline__ void gj16s(const float* Psrc, float* dst, int lane) {
    const int r  = lane & 15;
    const int h  = (lane >> 4) & 1;
    const int c0 = h << 3;
    float a[8];
    #pragma unroll
    for (int j = 0; j < 8; ++j) a[j] = Psrc[r * LS + c0 + j];
    #pragma unroll
    for (int k = 0; k < 16; ++k) {
        const int kh = k >> 3, kc = k & 7;
        float p   = __shfl_sync(0xffffffffu, a[kc], k + (kh << 4)); // a[k][k]
        float inv = __fdividef(1.0f, p);
        float f   = __shfl_sync(0xffffffffu, a[kc], r + (kh << 4)); // a[r][k]
        float fi  = f * inv;
        bool  isk = (r == k);
        #pragma unroll
        for (int j = 0; j < 8; ++j) {
            float rkj = __shfl_sync(0xffffffffu, a[j], k + (h << 4)); // a[k][c0+j]
            float rs  = rkj * inv;
            float upd = a[j] - fi * rkj;
            a[j] = isk ? rs : upd;
        }
        if (h == kh) a[kc] = isk ? inv : -fi;  // column-k fixup
    }
    #pragma unroll
    for (int j = 0; j < 8; ++j) dst[r * LS + c0 + j] = a[j];
}

__global__ __launch_bounds__(NTHR, 1)
void mpc_kernel(const float* __restrict__ x0g, const float* __restrict__ Qg,
                const float* __restrict__ cg,  const float* __restrict__ Ag,
                const float* __restrict__ Bg,  const float* __restrict__ log_,
                const float* __restrict__ upg, float* __restrict__ out, int NB)
{
    extern __shared__ float smraw[];
    Smem* S = reinterpret_cast<Smem*>(smraw);
    const int b    = blockIdx.x;
    const int tid  = threadIdx.x;
    const int wid  = tid >> 5;
    const int lane = tid & 31;

    // ---------------- load inputs ----------------
    for (int i = tid; i < NZd; i += NTHR) {
        S->z[i]  = 0.f;
        S->Qd[i] = Qg[b * NZd + i];
        S->cd[i] = cg[b * NZd + i];
    }
    for (int i = tid; i < NEQ; i += NTHR) S->lamE[i] = 0.f;
    for (int i = tid; i < NIN; i += NTHR) {
        S->lamU[i] = 0.f; S->lamL[i] = 0.f;
        S->lo[i]  = log_[b * NIN + i];
        S->up[i]  = upg[b * NIN + i];
        S->act[i] = -1;
    }
    for (int i = tid; i < 192; i += NTHR) {
        int r = i / 16, cc = i % 16;
        S->M[i] = (cc < 12) ? Ag[r * 12 + cc] : Bg[r * 4 + (cc - 12)];
    }
    if (tid < 12) S->x0[tid] = x0g[b * 12 + tid];
    __syncthreads();

    // ---------------- MtM ----------------
    for (int e = tid; e < 256; e += NTHR) {
        int ri = e >> 4, rj = e & 15;
        float a = 0.f;
        #pragma unroll
        for (int k = 0; k < 12; ++k) a += S->M[k * 16 + ri] * S->M[k * 16 + rj];
        S->MtM[e] = a;
    }

    // ---------------- initial rollout (warp 0) ----------------
    if (tid < 32) {
        if (tid < 12) S->z[tid] = S->x0[tid];
        for (int t = 0; t < Td - 1; ++t) {
            __syncwarp();
            if (tid < 12) {
                float acc = 0.f;
                #pragma unroll
                for (int j = 0; j < 12; ++j) acc += S->M[tid * 16 + j] * S->z[t * 16 + j];
                S->z[(t + 1) * 16 + tid] = acc;
            }
        }
    }
    __syncthreads();

    float rho = 1.f;
    for (int al = 0; al < 3; ++al) {
        for (int nt = 0; nt < 3; ++nt) {
            // ---- Yv = rho*r + lamE (also reset flip range) ----
            if (tid == 0) { S->fmin = 32; S->fmax = -1; }
            for (int idx = tid; idx < NEQ; idx += NTHR) {
                int t = idx / 12, i = idx % 12;
                float r;
                if (t == 0) r = S->z[i] - S->x0[i];
                else {
                    float acc = S->z[t * 16 + i];
                    const float* zp = &S->z[(t - 1) * 16];
                    const float* Mr = &S->M[i * 16];
                    #pragma unroll
                    for (int k = 0; k < 16; ++k) acc -= Mr[k] * zp[k];
                    r = acc;
                }
                S->Yv[idx] = rho * r + S->lamE[idx];
            }
            __syncthreads();
            // ---- gradient + active-set flip tracking ----
            for (int idx = tid; idx < NZd; idx += NTHR) {
                int t = idx >> 4, i = idx & 15;
                float gv = S->Qd[idx] * S->z[idx] + S->cd[idx];
                if (i < 12) gv += S->Yv[t * 12 + i];
                if (t < Td - 1) {
                    const float* Yn = &S->Yv[(t + 1) * 12];
                    float acc = 0.f;
                    #pragma unroll
                    for (int k = 0; k < 12; ++k) acc += S->M[k * 16 + i] * Yn[k];
                    gv -= acc;
                }
                if (i >= 12) {
                    int u = t * 4 + (i - 12);
                    float su = fmaxf(rho * (S->z[idx] - S->up[u]) + S->lamU[u], 0.f);
                    float sl = fmaxf(rho * (S->lo[u] - S->z[idx]) + S->lamL[u], 0.f);
                    gv += su - sl;
                    int a = (su > 0.f ? 1 : 0) | (sl > 0.f ? 2 : 0);
                    if (a != S->act[u]) {
                        S->act[u] = a;
                        atomicMin(&S->fmin, t);
                        atomicMax(&S->fmax, t);
                    }
                }
                S->g[idx] = gv;
            }
            __syncthreads();
            int fmn = (nt == 0) ? 0  : S->fmin;
            int fmx = (nt == 0) ? 31 : S->fmax;
            bool needFactor = (nt == 0) || (fmx >= 0);

            if (needFactor) {
                int sstart = min(fmn, 31 - fmx);
                if (sstart < 0) sstart = 0;
                if (sstart > 15) sstart = 16;   // only middle needs redo
                for (int s = sstart; s < 16; ++s) {
                    const int tf = s, tb = 31 - s;
                    const bool doF  = (tf >= fmn);
                    const bool doFU = doF && (tf > 0) && (tf - 1 >= fmn);
                    const bool doB  = (s < 15) && (fmx >= tb);
                    const bool doBU = doB && (fmx >= tb + 1);
                    // U builds (row-local writes; readers row-local in same warp)
                    for (int e = tid; e < 256; e += NTHR) {
                        int ri = e >> 4, rj = e & 15;
                        if (doFU) {
                            float v = 0.f;
                            if (ri < 12) {
                                const float* Pp = &S->inv[(tf - 1) * 16 * LS];
                                const float* Mr = &S->M[ri * 16];
                                float a0 = 0.f, a1 = 0.f;
                                #pragma unroll
                                for (int m = 0; m < 16; m += 2) {
                                    a0 += Mr[m]     * Pp[m * LS + rj];
                                    a1 += Mr[m + 1] * Pp[(m + 1) * LS + rj];
                                }
                                v = rho * (a0 + a1);
                            }
                            S->Uf[tf * 16 * LS + ri * LS + rj] = v;
                        }
                        if (doBU) {
                            const float* Qp = &S->inv[(tb + 1) * 16 * LS];
                            float a0 = 0.f, a1 = 0.f;
                            #pragma unroll
                            for (int m = 0; m < 12; m += 2) {
                                a0 += S->M[m * 16 + ri]       * Qp[m * LS + rj];
                                a1 += S->M[(m + 1) * 16 + ri] * Qp[(m + 1) * LS + rj];
                            }
                            S->Ub[tb * 16 * LS + ri * LS + rj] = rho * (a0 + a1);
                        }
                    }
                    __syncwarp();
                    // P builds
                    for (int e = tid; e < 256; e += NTHR) {
                        int ri = e >> 4, rj = e & 15;
                        if (doF) {
                            float v = buildD(S, tf, ri, rj, rho);
                            if (tf > 0 && ri < 12 && rj < 12) {
                                const float* Ur = &S->Uf[tf * 16 * LS + ri * LS];
                                const float* Mr = &S->M[rj * 16];
                                float a0 = 0.f, a1 = 0.f;
                                #pragma unroll
                                for (int k = 0; k < 16; k += 2) { a0 += Ur[k] * Mr[k]; a1 += Ur[k+1] * Mr[k+1]; }
                                v -= rho * (a0 + a1);
                            }
                            S->Pa[ri * LS + rj] = v;
                        }
                        if (doB) {
                            float v = buildD(S, tb, ri, rj, rho);
                            if (s > 0) {
                                const float* Ur = &S->Ub[tb * 16 * LS + ri * LS];
                                float a0 = 0.f, a1 = 0.f;
                                #pragma unroll
                                for (int k = 0; k < 12; k += 2) {
                                    a0 += Ur[k]     * S->M[k * 16 + rj];
                                    a1 += Ur[k + 1] * S->M[(k + 1) * 16 + rj];
                                }
                                v -= rho * (a0 + a1);
                            }
                            S->Pb[ri * LS + rj] = v;
                        }
                    }
                    __syncthreads();
                    if (wid == 0 && doF)      gj16s(S->Pa, &S->inv[tf * 16 * LS], lane);
                    else if (wid == 1 && doB) gj16s(S->Pb, &S->inv[tb * 16 * LS], lane);
                    __syncthreads();
                }
                // ---- middle block t=16 ----
                {
                    const bool doMUf = (fmn <= 15);
                    const bool doMUb = (fmx >= 17);
                    for (int e = tid; e < 256; e += NTHR) {
                        int ri = e >> 4, rj = e & 15;
                        if (doMUf) {
                            float v = 0.f;
                            if (ri < 12) {
                                const float* Pp = &S->inv[15 * 16 * LS];
                                const float* Mr = &S->M[ri * 16];
                                float a0 = 0.f, a1 = 0.f;
                                #pragma unroll
                                for (int m = 0; m < 16; m += 2) {
                                    a0 += Mr[m] * Pp[m * LS + rj];
                                    a1 += Mr[m + 1] * Pp[(m + 1) * LS + rj];
                                }
                                v = rho * (a0 + a1);
                            }
                            S->Uf[16 * 16 * LS + ri * LS + rj] = v;
                        }
                        if (doMUb) {
                            const float* Qp = &S->inv[17 * 16 * LS];
                            float a0 = 0.f, a1 = 0.f;
                            #pragma unroll
                            for (int m = 0; m < 12; m += 2) {
                                a0 += S->M[m * 16 + ri] * Qp[m * LS + rj];
                                a1 += S->M[(m + 1) * 16 + ri] * Qp[(m + 1) * LS + rj];
                            }
                            S->Ub[16 * 16 * LS + ri * LS + rj] = rho * (a0 + a1);
                        }
                    }
                    __syncwarp();
                    for (int e = tid; e < 256; e += NTHR) {
                        int ri = e >> 4, rj = e & 15;
                        float pv = buildD(S, 16, ri, rj, rho);
                        if (ri < 12 && rj < 12) {
                            const float* Ur = &S->Uf[16 * 16 * LS + ri * LS];
                            const float* Mr = &S->M[rj * 16];
                            float a0 = 0.f;
                            #pragma unroll
                            for (int k = 0; k < 16; ++k) a0 += Ur[k] * Mr[k];
                            pv -= rho * a0;
                        }
                        {
                            const float* Ur = &S->Ub[16 * 16 * LS + ri * LS];
                            float a0 = 0.f;
                            #pragma unroll
                            for (int k = 0; k < 12; ++k) a0 += Ur[k] * S->M[k * 16 + rj];
                            pv -= rho * a0;
                        }
                        S->Pa[ri * LS + rj] = pv;
                    }
                    __syncthreads();
                    if (wid == 0) gj16s(S->Pa, &S->inv[16 * 16 * LS], lane);
                    __syncthreads();
                }
            }

            // ---- elimination sweeps (warp 0 fwd, warp 1 bwd, concurrent) ----
            if (wid == 0) {
                float w = (lane < 16) ? S->g[lane] : 0.f;           // t=0
                for (int t = 1; t <= 15; ++t) {
                    float gv = (lane < 16) ? S->g[t * 16 + lane] : 0.f;
                    const float* Ur = &S->Uf[t * 16 * LS + (lane & 15) * LS];
                    float a0 = 0.f, a1 = 0.f;
                    #pragma unroll
                    for (int k = 0; k < 16; k += 2) {
                        a0 += Ur[k]     * __shfl_sync(0xffffffffu, w, k);
                        a1 += Ur[k + 1] * __shfl_sync(0xffffffffu, w, k + 1);
                    }
                    w = gv + a0 + a1;
                    if (lane < 16) S->g[t * 16 + lane] = w;
                }
            } else if (wid == 1) {
                float w = (lane < 16) ? S->g[31 * 16 + lane] : 0.f; // t=31
                for (int t = 30; t >= 17; --t) {
                    float gv = (lane < 16) ? S->g[t * 16 + lane] : 0.f;
                    const float* Ur = &S->Ub[t * 16 * LS + (lane & 15) * LS];
                    float a0 = 0.f, a1 = 0.f;
                    #pragma unroll
                    for (int k = 0; k < 16; k += 2) {
                        a0 += Ur[k]     * __shfl_sync(0xffffffffu, w, k);
                        a1 += Ur[k + 1] * __shfl_sync(0xffffffffu, w, k + 1);
                    }
                    w = gv + a0 + a1;
                    if (lane < 16) S->g[t * 16 + lane] = w;
                }
            }
            __syncthreads();
            // ---- middle rhs: w_16 += Uf16 w_15 + Ub16 w_17 (warp 0) ----
            if (wid == 0 && lane < 16) {
                const float* Uf16 = &S->Uf[16 * 16 * LS + lane * LS];
                const float* Ub16 = &S->Ub[16 * 16 * LS + lane * LS];
                const float* w15  = &S->g[15 * 16];
                const float* w17  = &S->g[17 * 16];
                float acc = S->g[16 * 16 + lane];
                #pragma unroll
                for (int k = 0; k < 16; ++k) acc += Uf16[k] * w15[k] + Ub16[k] * w17[k];
                S->g[16 * 16 + lane] = acc;
            }
            __syncthreads();
            // ---- parallel: Pw_t = inv_t * w_t ----
            for (int idx = tid; idx < NZd; idx += NTHR) {
                int t = idx >> 4, i = idx & 15;
                const float* Pi = &S->inv[t * 16 * LS + i * LS];
                const float* wv = &S->g[t * 16];
                float a0 = 0.f, a1 = 0.f;
                #pragma unroll
                for (int k = 0; k < 16; k += 2) { a0 += Pi[k] * wv[k]; a1 += Pi[k+1] * wv[k+1]; }
                S->Pw[idx] = a0 + a1;
            }
            __syncthreads();
            // ---- outward passes (warp 0 down, warp 1 up, concurrent) ----
            if (wid == 0) {
                float dz = (lane < 16) ? S->Pw[16 * 16 + lane] : 0.f;
                if (lane < 16) S->g[16 * 16 + lane] = dz;
                for (int t = 15; t >= 0; --t) {
                    float acc = (lane < 16) ? S->Pw[t * 16 + lane] : 0.f;
                    const float* Uc = &S->Uf[(t + 1) * 16 * LS];
                    #pragma unroll
                    for (int k = 0; k < 12; ++k)
                        acc += Uc[k * LS + (lane & 15)] * __shfl_sync(0xffffffffu, dz, k);
                    dz = acc;
                    if (lane < 16) S->g[t * 16 + lane] = dz;
                }
            } else if (wid == 1) {
                float dz = (lane < 16) ? S->Pw[16 * 16 + lane] : 0.f;
                for (int t = 17; t <= 31; ++t) {
                    float acc = (lane < 16) ? S->Pw[t * 16 + lane] : 0.f;
                    const float* Uc = &S->Ub[(t - 1) * 16 * LS];
                    #pragma unroll
                    for (int k = 0; k < 16; ++k)
                        acc += Uc[k * LS + (lane & 15)] * __shfl_sync(0xffffffffu, dz, k);
                    dz = acc;
                    if (lane < 16) S->g[t * 16 + lane] = dz;
                }
            }
            __syncthreads();
            // ---- z -= dz ----
            for (int idx = tid; idx < NZd; idx += NTHR) S->z[idx] -= S->g[idx];
            __syncthreads();
        } // newton

        // ---- multiplier updates ----
        for (int idx = tid; idx < NEQ; idx += NTHR) {
            int t = idx / 12, i = idx % 12;
            float r;
            if (t == 0) r = S->z[i] - S->x0[i];
            else {
                float acc = S->z[t * 16 + i];
                const float* zp = &S->z[(t - 1) * 16];
                const float* Mr = &S->M[i * 16];
                #pragma unroll
                for (int k = 0; k < 16; ++k) acc -= Mr[k] * zp[k];
                r = acc;
            }
            S->lamE[idx] += rho * r;
        }
        for (int idx = tid; idx < NIN; idx += NTHR) {
            int t = idx >> 2, j = idx & 3;
            float uv = S->z[t * 16 + 12 + j];
            S->lamU[idx] = fmaxf(S->lamU[idx] + rho * (uv - S->up[idx]), 0.f);
            S->lamL[idx] = fmaxf(S->lamL[idx] + rho * (S->lo[idx] - uv), 0.f);
        }
        __syncthreads();
        rho = fminf(rho * 10.f, 100.f);
    } // al

    // ---------------- outputs: x [NB,T,NS] then u [NB,T,NC] ----------------
    for (int idx = tid; idx < NEQ; idx += NTHR) {
        int t = idx / 12, i = idx % 12;
        out[b * (Td * NSd) + idx] = S->z[t * 16 + i];
    }
    for (int idx = tid; idx < NIN; idx += NTHR) {
        int t = idx >> 2, j = idx & 3;
        out[NB * (Td * NSd) + b * (Td * NCd) + idx] = S->z[t * 16 + 12 + j];
    }
}

extern "C" void kernel_launch(void* const* d_in, const int* in_sizes, int n_in,
                              void* d_out, int out_size)
{
    const float* x0 = (const float*)d_in[0];
    const float* Q  = (const float*)d_in[1];
    const float* c  = (const float*)d_in[2];
    const float* A  = (const float*)d_in[3];
    const float* B  = (const float*)d_in[4];
    const float* lo = (const float*)d_in[5];
    const float* up = (const float*)d_in[6];
    float* out = (float*)d_out;

    int NB = in_sizes[0] / NSd;   // 64
    size_t smem = sizeof(Smem);
    cudaFuncSetAttribute(mpc_kernel, cudaFuncAttributeMaxDynamicSharedMemorySize, (int)smem);
    mpc_kernel<<<NB, NTHR, smem>>>(x0, Q, c, A, B, lo, up, out, NB);
}